// round 8
// baseline (speedup 1.0000x reference)
#include <cuda_runtime.h>
#include <math.h>
#include <stdint.h>

#define NN 100000
#define EE 1600000
#define GG 64

// ---------------- scratch (device globals; no allocation allowed) ----------
__device__ float    g_h[NN * 128];
__device__ uint32_t g_hb[NN * 64];      // bf16x2 shadow of g_h (gather source)
__device__ float    g_agg[NN * 128];
__device__ float    g_z[NN * 256];
__device__ double   g_sum[256];
__device__ double   g_sumsq[256];
__device__ float    g_scale[256];
__device__ float    g_shift[256];
__device__ float    g_pool[2 * GG * 128];
__device__ float    g_cnt[2 * GG];
__device__ float    g_fc1o[GG * 256];
__device__ float    g_fc2o[GG * 64];

// ---------------- helpers ---------------------------------------------------
__device__ __forceinline__ void split2(float e0, float e1, uint32_t& hp, uint32_t& lp) {
    asm("cvt.rn.bf16x2.f32 %0, %1, %2;" : "=r"(hp) : "f"(e1), "f"(e0));
    float h0 = __uint_as_float(hp << 16);
    float h1 = __uint_as_float(hp & 0xFFFF0000u);
    float l0 = e0 - h0, l1 = e1 - h1;
    asm("cvt.rn.bf16x2.f32 %0, %1, %2;" : "=r"(lp) : "f"(l1), "f"(l0));
}

__device__ __forceinline__ void mma16816(float* c, const uint32_t* a, const uint32_t* b) {
    asm volatile("mma.sync.aligned.m16n8k16.row.col.f32.bf16.bf16.f32 "
                 "{%0,%1,%2,%3}, {%4,%5,%6,%7}, {%8,%9}, {%0,%1,%2,%3};"
                 : "+f"(c[0]), "+f"(c[1]), "+f"(c[2]), "+f"(c[3])
                 : "r"(a[0]), "r"(a[1]), "r"(a[2]), "r"(a[3]), "r"(b[0]), "r"(b[1]));
}

// ---------------- bf16x3 mma.sync GEMM (R5 structure + fused epilogues) ------
// MODE 0: g_h[N,128] = Aext[N,1024] @ B[1024,128] + bias            (+ g_hb)
// MODE 1: g_z[N,256] = (g_agg + (1+eps)*g_h)[N,128] @ B[128,256] + bias
//          (grid.y = 2; accumulates BN sum/sumsq into g_sum/g_sumsq)
// MODE 2: g_h[N,128] = relu(relu(BN(g_z))[N,256] @ B[256,128] + bias + g_h) (+ g_hb)
#define AS 40   // smem row stride in bf16 elems (80 B)

template <int MODE>
__global__ __launch_bounds__(256)
void mma_gemm(const float* __restrict__ Aext, const float* __restrict__ Bg,
              const float* __restrict__ bias, const float* __restrict__ epsp)
{
    constexpr int K   = (MODE == 0) ? 1024 : ((MODE == 1) ? 128 : 256);
    constexpr int LDB = (MODE == 1) ? 256 : 128;
    constexpr int LDC = (MODE == 1) ? 256 : 128;
    constexpr int NCHUNK = K / 32;
    const float* A = (MODE == 0) ? Aext : ((MODE == 1) ? g_agg : g_z);
    float* C = (MODE == 1) ? g_z : g_h;

    __shared__ __align__(16) uint16_t Ahi[128 * AS], Alo[128 * AS];
    __shared__ __align__(16) uint16_t Bhi[128 * AS], Blo[128 * AS];
    __shared__ float s_sum[128], s_sumsq[128];

    const int tid  = threadIdx.x;
    const int lane = tid & 31, wid = tid >> 5;
    const int bm = blockIdx.x * 128;
    const int bn = blockIdx.y * 128;
    const int wm = (wid >> 1) * 32;
    const int wn = (wid & 1) * 64;
    const int grp = lane >> 2, qid = lane & 3;

    if (MODE == 1 && tid < 128) { s_sum[tid] = 0.f; s_sumsq[tid] = 0.f; }
    const float ee = (MODE == 1) ? (1.0f + __ldg(epsp)) : 0.0f;

    float acc[2][8][4];
#pragma unroll
    for (int mt = 0; mt < 2; mt++)
#pragma unroll
        for (int nt = 0; nt < 8; nt++)
#pragma unroll
            for (int q = 0; q < 4; q++) acc[mt][nt][q] = 0.f;

    const int arow = tid >> 1, ahalf = tid & 1;        // A loader: row, 16-col half
    const int bnid = tid & 127, bkh = (tid >> 7) * 16; // B loader: n col, 16-k half
    const int rA = bm + arow;

    auto loadA = [&](int k0, float* v) {
        if (rA < NN) {
            const float* ap = A + (size_t)rA * K + k0 + ahalf * 16;
#pragma unroll
            for (int q = 0; q < 4; q++)
                *reinterpret_cast<float4*>(v + 4 * q) =
                    __ldg(reinterpret_cast<const float4*>(ap + 4 * q));
            if (MODE == 1) {
                const float* hp = g_h + (size_t)rA * 128 + k0 + ahalf * 16;
#pragma unroll
                for (int q = 0; q < 4; q++) {
                    float4 hv = __ldg(reinterpret_cast<const float4*>(hp + 4 * q));
                    v[4 * q + 0] = fmaf(ee, hv.x, v[4 * q + 0]);
                    v[4 * q + 1] = fmaf(ee, hv.y, v[4 * q + 1]);
                    v[4 * q + 2] = fmaf(ee, hv.z, v[4 * q + 2]);
                    v[4 * q + 3] = fmaf(ee, hv.w, v[4 * q + 3]);
                }
            }
        } else {
#pragma unroll
            for (int j = 0; j < 16; j++) v[j] = 0.f;
        }
        if (MODE == 2) {
            const int kb = k0 + ahalf * 16;
#pragma unroll
            for (int j = 0; j < 16; j++)
                v[j] = fmaxf(fmaf(v[j], g_scale[kb + j], g_shift[kb + j]), 0.f);
        }
    };
    auto loadB = [&](int k0, float* v) {
        const float* bp = Bg + (size_t)(k0 + bkh) * LDB + bn + bnid;
#pragma unroll
        for (int j = 0; j < 16; j++) v[j] = __ldg(bp + (size_t)j * LDB);
    };
    auto storeA = [&](const float* v) {
#pragma unroll
        for (int q = 0; q < 2; q++) {
            uint32_t hs[4], ls[4];
#pragma unroll
            for (int p = 0; p < 4; p++)
                split2(v[q * 8 + p * 2], v[q * 8 + p * 2 + 1], hs[p], ls[p]);
            const int c = ahalf * 16 + q * 8;
            *reinterpret_cast<uint4*>(&Ahi[arow * AS + c]) = make_uint4(hs[0], hs[1], hs[2], hs[3]);
            *reinterpret_cast<uint4*>(&Alo[arow * AS + c]) = make_uint4(ls[0], ls[1], ls[2], ls[3]);
        }
    };
    auto storeB = [&](const float* v) {
#pragma unroll
        for (int q = 0; q < 2; q++) {
            uint32_t hs[4], ls[4];
#pragma unroll
            for (int p = 0; p < 4; p++)
                split2(v[q * 8 + p * 2], v[q * 8 + p * 2 + 1], hs[p], ls[p]);
            const int c = bkh + q * 8;
            *reinterpret_cast<uint4*>(&Bhi[bnid * AS + c]) = make_uint4(hs[0], hs[1], hs[2], hs[3]);
            *reinterpret_cast<uint4*>(&Blo[bnid * AS + c]) = make_uint4(ls[0], ls[1], ls[2], ls[3]);
        }
    };
    auto mmaStep = [&]() {
#pragma unroll
        for (int s = 0; s < 32; s += 16) {
            uint32_t ah[2][4], al[2][4];
#pragma unroll
            for (int mt = 0; mt < 2; mt++) {
                const int r0 = (wm + mt * 16 + grp) * AS + s + qid * 2;
                const int r8 = r0 + 8 * AS;
                ah[mt][0] = *reinterpret_cast<const uint32_t*>(&Ahi[r0]);
                ah[mt][1] = *reinterpret_cast<const uint32_t*>(&Ahi[r8]);
                ah[mt][2] = *reinterpret_cast<const uint32_t*>(&Ahi[r0 + 8]);
                ah[mt][3] = *reinterpret_cast<const uint32_t*>(&Ahi[r8 + 8]);
                al[mt][0] = *reinterpret_cast<const uint32_t*>(&Alo[r0]);
                al[mt][1] = *reinterpret_cast<const uint32_t*>(&Alo[r8]);
                al[mt][2] = *reinterpret_cast<const uint32_t*>(&Alo[r0 + 8]);
                al[mt][3] = *reinterpret_cast<const uint32_t*>(&Alo[r8 + 8]);
            }
#pragma unroll
            for (int nt = 0; nt < 8; nt++) {
                const int nb = (wn + nt * 8 + grp) * AS + s + qid * 2;
                uint32_t bh[2], bl[2];
                bh[0] = *reinterpret_cast<const uint32_t*>(&Bhi[nb]);
                bh[1] = *reinterpret_cast<const uint32_t*>(&Bhi[nb + 8]);
                bl[0] = *reinterpret_cast<const uint32_t*>(&Blo[nb]);
                bl[1] = *reinterpret_cast<const uint32_t*>(&Blo[nb + 8]);
#pragma unroll
                for (int mt = 0; mt < 2; mt++) {
                    mma16816(acc[mt][nt], ah[mt], bh);
                    mma16816(acc[mt][nt], ah[mt], bl);
                    mma16816(acc[mt][nt], al[mt], bh);
                }
            }
        }
    };

    // ---- prologue: chunk 0 ----
    {
        float va[16], vb[16];
        loadA(0, va); loadB(0, vb);
        storeA(va);   storeB(vb);
    }
    __syncthreads();

    // ---- pipelined main loop: prefetch A and B before MMA (R5 structure) ----
    for (int ch = 0; ch < NCHUNK - 1; ch++) {
        float wa[16], wb[16];
        loadA((ch + 1) * 32, wa);
        loadB((ch + 1) * 32, wb);
        mmaStep();
        __syncthreads();
        storeA(wa); storeB(wb);
        __syncthreads();
    }
    mmaStep();

    // ---- epilogue (fused bias / residual / ReLU / bf16 shadow / BN stats) ----
#pragma unroll
    for (int nt = 0; nt < 8; nt++) {
        const int ccl = wn + nt * 8 + qid * 2;
        const int cc  = bn + ccl;
        const float b0 = bias[cc], b1 = bias[cc + 1];
        float cs0 = 0.f, cs1 = 0.f, cq0 = 0.f, cq1 = 0.f;
#pragma unroll
        for (int mt = 0; mt < 2; mt++) {
            const int r0 = bm + wm + mt * 16 + grp;
#pragma unroll
            for (int hrow = 0; hrow < 2; hrow++) {
                const int r = r0 + hrow * 8;
                if (r < NN) {
                    float2 o;
                    o.x = acc[mt][nt][hrow * 2 + 0] + b0;
                    o.y = acc[mt][nt][hrow * 2 + 1] + b1;
                    if (MODE == 2) {
                        const float2 h = *reinterpret_cast<const float2*>(&g_h[(size_t)r * 128 + cc]);
                        o.x = fmaxf(o.x + h.x, 0.f);
                        o.y = fmaxf(o.y + h.y, 0.f);
                    }
                    *reinterpret_cast<float2*>(&C[(size_t)r * LDC + cc]) = o;
                    if (MODE == 0 || MODE == 2) {
                        uint32_t hb;
                        asm("cvt.rn.bf16x2.f32 %0, %1, %2;" : "=r"(hb) : "f"(o.y), "f"(o.x));
                        g_hb[((size_t)r * 128 + cc) >> 1] = hb;
                    }
                    if (MODE == 1) {
                        cs0 += o.x; cq0 = fmaf(o.x, o.x, cq0);
                        cs1 += o.y; cq1 = fmaf(o.y, o.y, cq1);
                    }
                }
            }
        }
        if (MODE == 1) {
            atomicAdd(&s_sum[ccl],       cs0);
            atomicAdd(&s_sum[ccl + 1],   cs1);
            atomicAdd(&s_sumsq[ccl],     cq0);
            atomicAdd(&s_sumsq[ccl + 1], cq1);
        }
    }
    if (MODE == 1) {
        __syncthreads();
        if (tid < 128) {
            atomicAdd(&g_sum[bn + tid],   (double)s_sum[tid]);
            atomicAdd(&g_sumsq[bn + tid], (double)s_sumsq[tid]);
        }
    }
}

// ---------------- small utility kernels -----------------------------------
__global__ void zero_pool_kernel() {
    int i = blockIdx.x * 256 + threadIdx.x;
    g_pool[i] = 0.f;
    if (i < 2 * GG) g_cnt[i] = 0.f;
}

// warp per edge: gather bf16 row (256B), vector-reduce fp32 into agg[dst];
// block 0 zeroes the BN accumulators for the upcoming MODE1.
__global__ void scatter_kernel(const int* __restrict__ ei) {
    int idx = blockIdx.x * 256 + threadIdx.x;  // 200000 x 256 (== E*32)
    if (blockIdx.x == 0) { g_sum[threadIdx.x] = 0.0; g_sumsq[threadIdx.x] = 0.0; }
    int e = idx >> 5;
    int c = idx & 31;
    int src = __ldg(&ei[e]);
    int dst = __ldg(&ei[EE + e]);
    uint2 v = *reinterpret_cast<const uint2*>(&g_hb[src * 64 + c * 2]);
    float f0 = __uint_as_float(v.x << 16);
    float f1 = __uint_as_float(v.x & 0xFFFF0000u);
    float f2 = __uint_as_float(v.y << 16);
    float f3 = __uint_as_float(v.y & 0xFFFF0000u);
    float* p = &g_agg[dst * 128 + c * 4];
    asm volatile("red.global.add.v4.f32 [%0], {%1,%2,%3,%4};"
                 :: "l"(p), "f"(f0), "f"(f1), "f"(f2), "f"(f3) : "memory");
}

__global__ void bn_finalize_kernel(const float* __restrict__ gam,
                                   const float* __restrict__ bet) {
    int c = threadIdx.x;   // 256
    float mean = (float)(g_sum[c] / (double)NN);
    float var  = (float)(g_sumsq[c] / (double)NN) - mean * mean;
    float sc = gam[c] * rsqrtf(var + 1e-5f);
    g_scale[c] = sc;
    g_shift[c] = fmaf(-mean, sc, bet[c]);
}

__global__ void pool_kernel(const int* __restrict__ batch, int which) {
    int idx = blockIdx.x * 256 + threadIdx.x;   // 12500 x 256 (== N*32)
    int n = idx >> 5;
    int c = (idx & 31) << 2;
    int g = __ldg(&batch[n]);
    float4 v = *reinterpret_cast<const float4*>(&g_h[n * 128 + c]);
    float* p = &g_pool[(which * GG + g) * 128 + c];
    asm volatile("red.global.add.v4.f32 [%0], {%1,%2,%3,%4};"
                 :: "l"(p), "f"(v.x), "f"(v.y), "f"(v.z), "f"(v.w) : "memory");
    if ((idx & 31) == 0) atomicAdd(&g_cnt[which * GG + g], 1.0f);
}

__global__ void head1_kernel(const float* __restrict__ W, const float* __restrict__ b) {
    int g = blockIdx.x, j = threadIdx.x;   // 64 x 256
    __shared__ float xc[256];
    if (j < 128) xc[j] = g_pool[g * 128 + j] / fmaxf(g_cnt[g], 1.0f);
    else         xc[j] = g_pool[(GG + g) * 128 + (j - 128)] / fmaxf(g_cnt[GG + g], 1.0f);
    __syncthreads();
    float acc = b[j];
#pragma unroll 8
    for (int k = 0; k < 256; k++) acc = fmaf(xc[k], W[k * 256 + j], acc);
    g_fc1o[g * 256 + j] = fmaxf(acc, 0.f);
}

__global__ void head2_kernel(const float* __restrict__ W, const float* __restrict__ b) {
    int g = blockIdx.x, j = threadIdx.x;   // 64 x 64
    __shared__ float xin[256];
    for (int k = j; k < 256; k += 64) xin[k] = g_fc1o[g * 256 + k];
    __syncthreads();
    float acc = b[j];
#pragma unroll 8
    for (int k = 0; k < 256; k++) acc = fmaf(xin[k], W[k * 64 + j], acc);
    g_fc2o[g * 64 + j] = fmaxf(acc, 0.f);
}

__global__ void head3_kernel(const float* __restrict__ W, const float* __restrict__ b,
                             float* __restrict__ out) {
    int g = threadIdx.x;   // 1 x 64
    float acc = b[0];
#pragma unroll
    for (int k = 0; k < 64; k++) acc = fmaf(g_fc2o[g * 64 + k], W[k], acc);
    out[g] = 1.0f / (1.0f + expf(-acc));
}

// ---------------- orchestration -------------------------------------------
extern "C" void kernel_launch(void* const* d_in, const int* in_sizes, int n_in,
                              void* d_out, int out_size) {
    const float* x[2]     = { (const float*)d_in[0], (const float*)d_in[3] };
    const int*   ei[2]    = { (const int*)d_in[1],   (const int*)d_in[4] };
    const int*   batch[2] = { (const int*)d_in[2],   (const int*)d_in[5] };

    void* aggp = nullptr;
    cudaGetSymbolAddress(&aggp, g_agg);

    const int GRID_M = (NN + 127) / 128;   // 782

    zero_pool_kernel<<<64, 256>>>();

    for (int b = 0; b < 2; b++) {
        int o = 6 + b * 9;
        const float* embW = (const float*)d_in[o + 0];
        const float* embB = (const float*)d_in[o + 1];
        const float* W1   = (const float*)d_in[o + 2];
        const float* b1   = (const float*)d_in[o + 3];
        const float* gam  = (const float*)d_in[o + 4];
        const float* bet  = (const float*)d_in[o + 5];
        const float* W2   = (const float*)d_in[o + 6];
        const float* b2   = (const float*)d_in[o + 7];
        const float* eps  = (const float*)d_in[o + 8];

        mma_gemm<0><<<dim3(GRID_M, 1), 256>>>(x[b], embW, embB, nullptr);

        for (int i = 0; i < 4; i++) {
            cudaMemsetAsync(aggp, 0, (size_t)NN * 128 * sizeof(float), 0);
            scatter_kernel<<<200000, 256>>>(ei[b]);
            mma_gemm<1><<<dim3(GRID_M, 2), 256>>>(nullptr, W1 + (size_t)i * 128 * 256,
                                                  b1 + i * 256, eps + i);
            bn_finalize_kernel<<<1, 256>>>(gam + i * 256, bet + i * 256);
            mma_gemm<2><<<dim3(GRID_M, 1), 256>>>(nullptr, W2 + (size_t)i * 256 * 128,
                                                  b2 + i * 128, nullptr);
        }
        pool_kernel<<<12500, 256>>>(batch[b], b);
    }

    head1_kernel<<<64, 256>>>((const float*)d_in[24], (const float*)d_in[25]);
    head2_kernel<<<64, 64>>>((const float*)d_in[26], (const float*)d_in[27]);
    head3_kernel<<<1, 64>>>((const float*)d_in[28], (const float*)d_in[29], (float*)d_out);
}

// round 9
// speedup vs baseline: 1.1167x; 1.1167x over previous
#include <cuda_runtime.h>
#include <math.h>
#include <stdint.h>

#define NN 100000
#define EE 1600000
#define GG 64

// ---------------- scratch (device globals; no allocation allowed) ----------
__device__ float    g_h[NN * 128];
__device__ uint32_t g_hb[NN * 64];      // bf16x2 shadow of g_h (gather source)
__device__ float    g_agg[NN * 128];
__device__ float    g_z[NN * 256];
__device__ double   g_sum[256];
__device__ double   g_sumsq[256];
__device__ float    g_scale[256];
__device__ float    g_shift[256];
__device__ float    g_pool[2 * GG * 128];
__device__ float    g_cnt[2 * GG];
__device__ float    g_fc1o[GG * 256];
__device__ float    g_fc2o[GG * 64];

// ---------------- helpers ---------------------------------------------------
__device__ __forceinline__ uint32_t cvt2(float e0, float e1) {
    uint32_t p;
    asm("cvt.rn.bf16x2.f32 %0, %1, %2;" : "=r"(p) : "f"(e1), "f"(e0));
    return p;
}

__device__ __forceinline__ void mma16816(float* c, const uint32_t* a, const uint32_t* b) {
    asm volatile("mma.sync.aligned.m16n8k16.row.col.f32.bf16.bf16.f32 "
                 "{%0,%1,%2,%3}, {%4,%5,%6,%7}, {%8,%9}, {%0,%1,%2,%3};"
                 : "+f"(c[0]), "+f"(c[1]), "+f"(c[2]), "+f"(c[3])
                 : "r"(a[0]), "r"(a[1]), "r"(a[2]), "r"(a[3]), "r"(b[0]), "r"(b[1]));
}

// ---------------- bf16 mma.sync GEMM (single term, fused epilogues) ----------
// MODE 0: g_h[N,128] = Aext[N,1024] @ B[1024,128] + bias            (+ g_hb)
// MODE 1: g_z[N,256] = (g_agg + (1+eps)*g_h)[N,128] @ B[128,256] + bias
//          (grid.y = 2; accumulates BN sum/sumsq into g_sum/g_sumsq)
// MODE 2: g_h[N,128] = relu(relu(BN(g_z))[N,256] @ B[256,128] + bias + g_h) (+ g_hb)
#define AS 40   // smem row stride in bf16 elems (80 B)

template <int MODE>
__global__ __launch_bounds__(256)
void mma_gemm(const float* __restrict__ Aext, const float* __restrict__ Bg,
              const float* __restrict__ bias, const float* __restrict__ epsp)
{
    constexpr int K   = (MODE == 0) ? 1024 : ((MODE == 1) ? 128 : 256);
    constexpr int LDB = (MODE == 1) ? 256 : 128;
    constexpr int LDC = (MODE == 1) ? 256 : 128;
    constexpr int NCHUNK = K / 32;
    const float* A = (MODE == 0) ? Aext : ((MODE == 1) ? g_agg : g_z);
    float* C = (MODE == 1) ? g_z : g_h;

    __shared__ __align__(16) uint16_t Ahi[128 * AS];
    __shared__ __align__(16) uint16_t Bhi[128 * AS];
    __shared__ float s_sum[128], s_sumsq[128];

    const int tid  = threadIdx.x;
    const int lane = tid & 31, wid = tid >> 5;
    const int bm = blockIdx.x * 128;
    const int bn = blockIdx.y * 128;
    const int wm = (wid >> 1) * 32;
    const int wn = (wid & 1) * 64;
    const int grp = lane >> 2, qid = lane & 3;

    if (MODE == 1 && tid < 128) { s_sum[tid] = 0.f; s_sumsq[tid] = 0.f; }
    const float ee = (MODE == 1) ? (1.0f + __ldg(epsp)) : 0.0f;

    float acc[2][8][4];
#pragma unroll
    for (int mt = 0; mt < 2; mt++)
#pragma unroll
        for (int nt = 0; nt < 8; nt++)
#pragma unroll
            for (int q = 0; q < 4; q++) acc[mt][nt][q] = 0.f;

    const int arow = tid >> 1, ahalf = tid & 1;        // A loader: row, 16-col half
    const int bnid = tid & 127, bkh = (tid >> 7) * 16; // B loader: n col, 16-k half
    const int rA = bm + arow;

    auto loadA = [&](int k0, float* v) {
        if (rA < NN) {
            const float* ap = A + (size_t)rA * K + k0 + ahalf * 16;
#pragma unroll
            for (int q = 0; q < 4; q++)
                *reinterpret_cast<float4*>(v + 4 * q) =
                    __ldg(reinterpret_cast<const float4*>(ap + 4 * q));
            if (MODE == 1) {
                const float* hp = g_h + (size_t)rA * 128 + k0 + ahalf * 16;
#pragma unroll
                for (int q = 0; q < 4; q++) {
                    float4 hv = __ldg(reinterpret_cast<const float4*>(hp + 4 * q));
                    v[4 * q + 0] = fmaf(ee, hv.x, v[4 * q + 0]);
                    v[4 * q + 1] = fmaf(ee, hv.y, v[4 * q + 1]);
                    v[4 * q + 2] = fmaf(ee, hv.z, v[4 * q + 2]);
                    v[4 * q + 3] = fmaf(ee, hv.w, v[4 * q + 3]);
                }
            }
        } else {
#pragma unroll
            for (int j = 0; j < 16; j++) v[j] = 0.f;
        }
        if (MODE == 2) {
            const int kb = k0 + ahalf * 16;
#pragma unroll
            for (int j = 0; j < 16; j++)
                v[j] = fmaxf(fmaf(v[j], g_scale[kb + j], g_shift[kb + j]), 0.f);
        }
    };
    auto loadB = [&](int k0, float* v) {
        const float* bp = Bg + (size_t)(k0 + bkh) * LDB + bn + bnid;
#pragma unroll
        for (int j = 0; j < 16; j++) v[j] = __ldg(bp + (size_t)j * LDB);
    };
    auto storeA = [&](const float* v) {
#pragma unroll
        for (int q = 0; q < 2; q++) {
            uint32_t hs[4];
#pragma unroll
            for (int p = 0; p < 4; p++)
                hs[p] = cvt2(v[q * 8 + p * 2], v[q * 8 + p * 2 + 1]);
            const int c = ahalf * 16 + q * 8;
            *reinterpret_cast<uint4*>(&Ahi[arow * AS + c]) = make_uint4(hs[0], hs[1], hs[2], hs[3]);
        }
    };
    auto storeB = [&](const float* v) {
#pragma unroll
        for (int q = 0; q < 2; q++) {
            uint32_t hs[4];
#pragma unroll
            for (int p = 0; p < 4; p++)
                hs[p] = cvt2(v[q * 8 + p * 2], v[q * 8 + p * 2 + 1]);
            const int c = bkh + q * 8;
            *reinterpret_cast<uint4*>(&Bhi[bnid * AS + c]) = make_uint4(hs[0], hs[1], hs[2], hs[3]);
        }
    };
    auto mmaStep = [&]() {
#pragma unroll
        for (int s = 0; s < 32; s += 16) {
            uint32_t ah[2][4];
#pragma unroll
            for (int mt = 0; mt < 2; mt++) {
                const int r0 = (wm + mt * 16 + grp) * AS + s + qid * 2;
                const int r8 = r0 + 8 * AS;
                ah[mt][0] = *reinterpret_cast<const uint32_t*>(&Ahi[r0]);
                ah[mt][1] = *reinterpret_cast<const uint32_t*>(&Ahi[r8]);
                ah[mt][2] = *reinterpret_cast<const uint32_t*>(&Ahi[r0 + 8]);
                ah[mt][3] = *reinterpret_cast<const uint32_t*>(&Ahi[r8 + 8]);
            }
#pragma unroll
            for (int nt = 0; nt < 8; nt++) {
                const int nb = (wn + nt * 8 + grp) * AS + s + qid * 2;
                uint32_t bh[2];
                bh[0] = *reinterpret_cast<const uint32_t*>(&Bhi[nb]);
                bh[1] = *reinterpret_cast<const uint32_t*>(&Bhi[nb + 8]);
#pragma unroll
                for (int mt = 0; mt < 2; mt++)
                    mma16816(acc[mt][nt], ah[mt], bh);
            }
        }
    };

    // ---- prologue: chunk 0 ----
    {
        float va[16], vb[16];
        loadA(0, va); loadB(0, vb);
        storeA(va);   storeB(vb);
    }
    __syncthreads();

    // ---- pipelined main loop: prefetch A and B before MMA ----
    for (int ch = 0; ch < NCHUNK - 1; ch++) {
        float wa[16], wb[16];
        loadA((ch + 1) * 32, wa);
        loadB((ch + 1) * 32, wb);
        mmaStep();
        __syncthreads();
        storeA(wa); storeB(wb);
        __syncthreads();
    }
    mmaStep();

    // ---- epilogue (fused bias / residual / ReLU / bf16 shadow / BN stats) ----
#pragma unroll
    for (int nt = 0; nt < 8; nt++) {
        const int ccl = wn + nt * 8 + qid * 2;
        const int cc  = bn + ccl;
        const float b0 = bias[cc], b1 = bias[cc + 1];
        float cs0 = 0.f, cs1 = 0.f, cq0 = 0.f, cq1 = 0.f;
#pragma unroll
        for (int mt = 0; mt < 2; mt++) {
            const int r0 = bm + wm + mt * 16 + grp;
#pragma unroll
            for (int hrow = 0; hrow < 2; hrow++) {
                const int r = r0 + hrow * 8;
                if (r < NN) {
                    float2 o;
                    o.x = acc[mt][nt][hrow * 2 + 0] + b0;
                    o.y = acc[mt][nt][hrow * 2 + 1] + b1;
                    if (MODE == 2) {
                        const float2 h = *reinterpret_cast<const float2*>(&g_h[(size_t)r * 128 + cc]);
                        o.x = fmaxf(o.x + h.x, 0.f);
                        o.y = fmaxf(o.y + h.y, 0.f);
                    }
                    *reinterpret_cast<float2*>(&C[(size_t)r * LDC + cc]) = o;
                    if (MODE == 0 || MODE == 2)
                        g_hb[((size_t)r * 128 + cc) >> 1] = cvt2(o.x, o.y);
                    if (MODE == 1) {
                        cs0 += o.x; cq0 = fmaf(o.x, o.x, cq0);
                        cs1 += o.y; cq1 = fmaf(o.y, o.y, cq1);
                    }
                }
            }
        }
        if (MODE == 1) {
            atomicAdd(&s_sum[ccl],       cs0);
            atomicAdd(&s_sum[ccl + 1],   cs1);
            atomicAdd(&s_sumsq[ccl],     cq0);
            atomicAdd(&s_sumsq[ccl + 1], cq1);
        }
    }
    if (MODE == 1) {
        __syncthreads();
        if (tid < 128) {
            atomicAdd(&g_sum[bn + tid],   (double)s_sum[tid]);
            atomicAdd(&g_sumsq[bn + tid], (double)s_sumsq[tid]);
        }
    }
}

// ---------------- small utility kernels -----------------------------------
__global__ void zero_pool_kernel() {
    int i = blockIdx.x * 256 + threadIdx.x;
    g_pool[i] = 0.f;
    if (i < 2 * GG) g_cnt[i] = 0.f;
}

// warp per edge: gather bf16 row (256B), vector-reduce fp32 into agg[dst];
// block 0 zeroes the BN accumulators for the upcoming MODE1.
__global__ void scatter_kernel(const int* __restrict__ ei) {
    int idx = blockIdx.x * 256 + threadIdx.x;  // 200000 x 256 (== E*32)
    if (blockIdx.x == 0) { g_sum[threadIdx.x] = 0.0; g_sumsq[threadIdx.x] = 0.0; }
    int e = idx >> 5;
    int c = idx & 31;
    int src = __ldg(&ei[e]);
    int dst = __ldg(&ei[EE + e]);
    uint2 v = *reinterpret_cast<const uint2*>(&g_hb[src * 64 + c * 2]);
    float f0 = __uint_as_float(v.x << 16);
    float f1 = __uint_as_float(v.x & 0xFFFF0000u);
    float f2 = __uint_as_float(v.y << 16);
    float f3 = __uint_as_float(v.y & 0xFFFF0000u);
    float* p = &g_agg[dst * 128 + c * 4];
    asm volatile("red.global.add.v4.f32 [%0], {%1,%2,%3,%4};"
                 :: "l"(p), "f"(f0), "f"(f1), "f"(f2), "f"(f3) : "memory");
}

__global__ void bn_finalize_kernel(const float* __restrict__ gam,
                                   const float* __restrict__ bet) {
    int c = threadIdx.x;   // 256
    float mean = (float)(g_sum[c] / (double)NN);
    float var  = (float)(g_sumsq[c] / (double)NN) - mean * mean;
    float sc = gam[c] * rsqrtf(var + 1e-5f);
    g_scale[c] = sc;
    g_shift[c] = fmaf(-mean, sc, bet[c]);
}

__global__ void pool_kernel(const int* __restrict__ batch, int which) {
    int idx = blockIdx.x * 256 + threadIdx.x;   // 12500 x 256 (== N*32)
    int n = idx >> 5;
    int c = (idx & 31) << 2;
    int g = __ldg(&batch[n]);
    float4 v = *reinterpret_cast<const float4*>(&g_h[n * 128 + c]);
    float* p = &g_pool[(which * GG + g) * 128 + c];
    asm volatile("red.global.add.v4.f32 [%0], {%1,%2,%3,%4};"
                 :: "l"(p), "f"(v.x), "f"(v.y), "f"(v.z), "f"(v.w) : "memory");
    if ((idx & 31) == 0) atomicAdd(&g_cnt[which * GG + g], 1.0f);
}

__global__ void head1_kernel(const float* __restrict__ W, const float* __restrict__ b) {
    int g = blockIdx.x, j = threadIdx.x;   // 64 x 256
    __shared__ float xc[256];
    if (j < 128) xc[j] = g_pool[g * 128 + j] / fmaxf(g_cnt[g], 1.0f);
    else         xc[j] = g_pool[(GG + g) * 128 + (j - 128)] / fmaxf(g_cnt[GG + g], 1.0f);
    __syncthreads();
    float acc = b[j];
#pragma unroll 8
    for (int k = 0; k < 256; k++) acc = fmaf(xc[k], W[k * 256 + j], acc);
    g_fc1o[g * 256 + j] = fmaxf(acc, 0.f);
}

__global__ void head2_kernel(const float* __restrict__ W, const float* __restrict__ b) {
    int g = blockIdx.x, j = threadIdx.x;   // 64 x 64
    __shared__ float xin[256];
    for (int k = j; k < 256; k += 64) xin[k] = g_fc1o[g * 256 + k];
    __syncthreads();
    float acc = b[j];
#pragma unroll 8
    for (int k = 0; k < 256; k++) acc = fmaf(xin[k], W[k * 64 + j], acc);
    g_fc2o[g * 64 + j] = fmaxf(acc, 0.f);
}

__global__ void head3_kernel(const float* __restrict__ W, const float* __restrict__ b,
                             float* __restrict__ out) {
    int g = threadIdx.x;   // 1 x 64
    float acc = b[0];
#pragma unroll
    for (int k = 0; k < 64; k++) acc = fmaf(g_fc2o[g * 64 + k], W[k], acc);
    out[g] = 1.0f / (1.0f + expf(-acc));
}

// ---------------- orchestration -------------------------------------------
extern "C" void kernel_launch(void* const* d_in, const int* in_sizes, int n_in,
                              void* d_out, int out_size) {
    const float* x[2]     = { (const float*)d_in[0], (const float*)d_in[3] };
    const int*   ei[2]    = { (const int*)d_in[1],   (const int*)d_in[4] };
    const int*   batch[2] = { (const int*)d_in[2],   (const int*)d_in[5] };

    void* aggp = nullptr;
    cudaGetSymbolAddress(&aggp, g_agg);

    const int GRID_M = (NN + 127) / 128;   // 782

    zero_pool_kernel<<<64, 256>>>();

    for (int b = 0; b < 2; b++) {
        int o = 6 + b * 9;
        const float* embW = (const float*)d_in[o + 0];
        const float* embB = (const float*)d_in[o + 1];
        const float* W1   = (const float*)d_in[o + 2];
        const float* b1   = (const float*)d_in[o + 3];
        const float* gam  = (const float*)d_in[o + 4];
        const float* bet  = (const float*)d_in[o + 5];
        const float* W2   = (const float*)d_in[o + 6];
        const float* b2   = (const float*)d_in[o + 7];
        const float* eps  = (const float*)d_in[o + 8];

        mma_gemm<0><<<dim3(GRID_M, 1), 256>>>(x[b], embW, embB, nullptr);

        for (int i = 0; i < 4; i++) {
            cudaMemsetAsync(aggp, 0, (size_t)NN * 128 * sizeof(float), 0);
            scatter_kernel<<<200000, 256>>>(ei[b]);
            mma_gemm<1><<<dim3(GRID_M, 2), 256>>>(nullptr, W1 + (size_t)i * 128 * 256,
                                                  b1 + i * 256, eps + i);
            bn_finalize_kernel<<<1, 256>>>(gam + i * 256, bet + i * 256);
            mma_gemm<2><<<dim3(GRID_M, 1), 256>>>(nullptr, W2 + (size_t)i * 256 * 128,
                                                  b2 + i * 128, nullptr);
        }
        pool_kernel<<<12500, 256>>>(batch[b], b);
    }

    head1_kernel<<<64, 256>>>((const float*)d_in[24], (const float*)d_in[25]);
    head2_kernel<<<64, 64>>>((const float*)d_in[26], (const float*)d_in[27]);
    head3_kernel<<<1, 64>>>((const float*)d_in[28], (const float*)d_in[29], (float*)d_out);
}

// round 10
// speedup vs baseline: 1.4975x; 1.3411x over previous
#include <cuda_runtime.h>
#include <math.h>
#include <stdint.h>

#define NN 100000
#define EE 1600000
#define GG 64

// ---------------- scratch (device globals; no allocation allowed) ----------
__device__ float    g_h[NN * 128];
__device__ uint32_t g_hb[NN * 64];      // bf16x2 shadow of g_h (gather source)
__device__ float    g_agg[NN * 128];
__device__ float    g_z[NN * 256];
__device__ double   g_sum[256];
__device__ double   g_sumsq[256];
__device__ float    g_scale[256];
__device__ float    g_shift[256];
__device__ float    g_pool[2 * GG * 128];
__device__ float    g_cnt[2 * GG];
__device__ float    g_fc1o[GG * 256];
__device__ float    g_fc2o[GG * 64];

// ---------------- helpers ---------------------------------------------------
__device__ __forceinline__ uint32_t cvt2(float e0, float e1) {
    uint32_t p;
    asm("cvt.rn.bf16x2.f32 %0, %1, %2;" : "=r"(p) : "f"(e1), "f"(e0));
    return p;
}

__device__ __forceinline__ void mma16816(float* c, const uint32_t* a, const uint32_t* b) {
    asm volatile("mma.sync.aligned.m16n8k16.row.col.f32.bf16.bf16.f32 "
                 "{%0,%1,%2,%3}, {%4,%5,%6,%7}, {%8,%9}, {%0,%1,%2,%3};"
                 : "+f"(c[0]), "+f"(c[1]), "+f"(c[2]), "+f"(c[3])
                 : "r"(a[0]), "r"(a[1]), "r"(a[2]), "r"(a[3]), "r"(b[0]), "r"(b[1]));
}

// ---------------- bf16 mma.sync GEMM (single term, 2 CTAs/SM) ---------------
// MODE 0: g_h[N,128] = Aext[N,1024] @ B[1024,128] + bias            (+ g_hb)
// MODE 1: g_z[N,256] = (g_agg + (1+eps)*g_h)[N,128] @ B[128,256] + bias
//          (grid.y = 2; accumulates BN sum/sumsq into g_sum/g_sumsq)
// MODE 2: g_h[N,128] = relu(relu(BN(g_z))[N,256] @ B[256,128] + bias + g_h) (+ g_hb)
#define AS 40   // smem row stride in bf16 elems (80 B)

template <int MODE>
__global__ __launch_bounds__(256, 2)
void mma_gemm(const float* __restrict__ Aext, const float* __restrict__ Bg,
              const float* __restrict__ bias, const float* __restrict__ epsp)
{
    constexpr int K   = (MODE == 0) ? 1024 : ((MODE == 1) ? 128 : 256);
    constexpr int LDB = (MODE == 1) ? 256 : 128;
    constexpr int LDC = (MODE == 1) ? 256 : 128;
    constexpr int NCHUNK = K / 32;
    const float* A = (MODE == 0) ? Aext : ((MODE == 1) ? g_agg : g_z);
    float* C = (MODE == 1) ? g_z : g_h;

    __shared__ __align__(16) uint16_t Ahi[128 * AS];
    __shared__ __align__(16) uint16_t Bhi[128 * AS];
    __shared__ float s_sum[128], s_sumsq[128];

    const int tid  = threadIdx.x;
    const int lane = tid & 31, wid = tid >> 5;
    const int bm = blockIdx.x * 128;
    const int bn = blockIdx.y * 128;
    const int wm = (wid >> 1) * 32;
    const int wn = (wid & 1) * 64;
    const int grp = lane >> 2, qid = lane & 3;

    if (MODE == 1 && tid < 128) { s_sum[tid] = 0.f; s_sumsq[tid] = 0.f; }
    const float ee = (MODE == 1) ? (1.0f + __ldg(epsp)) : 0.0f;

    float acc[2][8][4];
#pragma unroll
    for (int mt = 0; mt < 2; mt++)
#pragma unroll
        for (int nt = 0; nt < 8; nt++)
#pragma unroll
            for (int q = 0; q < 4; q++) acc[mt][nt][q] = 0.f;

    const int arow = tid >> 1, ahalf = tid & 1;        // A loader: row, 16-col half
    const int bnid = tid & 127, bkh = (tid >> 7) * 16; // B loader: n col, 16-k half
    const int rA = bm + arow;

    auto loadA = [&](int k0, float* v) {
        if (rA < NN) {
            const float* ap = A + (size_t)rA * K + k0 + ahalf * 16;
#pragma unroll
            for (int q = 0; q < 4; q++)
                *reinterpret_cast<float4*>(v + 4 * q) =
                    __ldg(reinterpret_cast<const float4*>(ap + 4 * q));
            if (MODE == 1) {
                const float* hp = g_h + (size_t)rA * 128 + k0 + ahalf * 16;
#pragma unroll
                for (int q = 0; q < 4; q++) {
                    float4 hv = __ldg(reinterpret_cast<const float4*>(hp + 4 * q));
                    v[4 * q + 0] = fmaf(ee, hv.x, v[4 * q + 0]);
                    v[4 * q + 1] = fmaf(ee, hv.y, v[4 * q + 1]);
                    v[4 * q + 2] = fmaf(ee, hv.z, v[4 * q + 2]);
                    v[4 * q + 3] = fmaf(ee, hv.w, v[4 * q + 3]);
                }
            }
        } else {
#pragma unroll
            for (int j = 0; j < 16; j++) v[j] = 0.f;
        }
        if (MODE == 2) {
            const int kb = k0 + ahalf * 16;
#pragma unroll
            for (int j = 0; j < 16; j++)
                v[j] = fmaxf(fmaf(v[j], g_scale[kb + j], g_shift[kb + j]), 0.f);
        }
    };
    auto loadB = [&](int k0, float* v) {
        const float* bp = Bg + (size_t)(k0 + bkh) * LDB + bn + bnid;
#pragma unroll
        for (int j = 0; j < 16; j++) v[j] = __ldg(bp + (size_t)j * LDB);
    };
    auto storeA = [&](const float* v) {
#pragma unroll
        for (int q = 0; q < 2; q++) {
            uint32_t hs[4];
#pragma unroll
            for (int p = 0; p < 4; p++)
                hs[p] = cvt2(v[q * 8 + p * 2], v[q * 8 + p * 2 + 1]);
            const int c = ahalf * 16 + q * 8;
            *reinterpret_cast<uint4*>(&Ahi[arow * AS + c]) = make_uint4(hs[0], hs[1], hs[2], hs[3]);
        }
    };
    auto storeB = [&](const float* v) {
#pragma unroll
        for (int q = 0; q < 2; q++) {
            uint32_t hs[4];
#pragma unroll
            for (int p = 0; p < 4; p++)
                hs[p] = cvt2(v[q * 8 + p * 2], v[q * 8 + p * 2 + 1]);
            const int c = bkh + q * 8;
            *reinterpret_cast<uint4*>(&Bhi[bnid * AS + c]) = make_uint4(hs[0], hs[1], hs[2], hs[3]);
        }
    };
    auto mmaStep = [&]() {
#pragma unroll
        for (int s = 0; s < 32; s += 16) {
            uint32_t ah[2][4];
#pragma unroll
            for (int mt = 0; mt < 2; mt++) {
                const int r0 = (wm + mt * 16 + grp) * AS + s + qid * 2;
                const int r8 = r0 + 8 * AS;
                ah[mt][0] = *reinterpret_cast<const uint32_t*>(&Ahi[r0]);
                ah[mt][1] = *reinterpret_cast<const uint32_t*>(&Ahi[r8]);
                ah[mt][2] = *reinterpret_cast<const uint32_t*>(&Ahi[r0 + 8]);
                ah[mt][3] = *reinterpret_cast<const uint32_t*>(&Ahi[r8 + 8]);
            }
#pragma unroll
            for (int nt = 0; nt < 8; nt++) {
                const int nb = (wn + nt * 8 + grp) * AS + s + qid * 2;
                uint32_t bh[2];
                bh[0] = *reinterpret_cast<const uint32_t*>(&Bhi[nb]);
                bh[1] = *reinterpret_cast<const uint32_t*>(&Bhi[nb + 8]);
#pragma unroll
                for (int mt = 0; mt < 2; mt++)
                    mma16816(acc[mt][nt], ah[mt], bh);
            }
        }
    };

    // ---- prologue: chunk 0 ----
    {
        float va[16], vb[16];
        loadA(0, va); loadB(0, vb);
        storeA(va);   storeB(vb);
    }
    __syncthreads();

    // ---- pipelined main loop: prefetch A and B before MMA ----
    for (int ch = 0; ch < NCHUNK - 1; ch++) {
        float wa[16], wb[16];
        loadA((ch + 1) * 32, wa);
        loadB((ch + 1) * 32, wb);
        mmaStep();
        __syncthreads();
        storeA(wa); storeB(wb);
        __syncthreads();
    }
    mmaStep();

    // ---- epilogue (fused bias / residual / ReLU / bf16 shadow / BN stats) ----
#pragma unroll
    for (int nt = 0; nt < 8; nt++) {
        const int ccl = wn + nt * 8 + qid * 2;
        const int cc  = bn + ccl;
        const float b0 = bias[cc], b1 = bias[cc + 1];
        float cs0 = 0.f, cs1 = 0.f, cq0 = 0.f, cq1 = 0.f;
#pragma unroll
        for (int mt = 0; mt < 2; mt++) {
            const int r0 = bm + wm + mt * 16 + grp;
#pragma unroll
            for (int hrow = 0; hrow < 2; hrow++) {
                const int r = r0 + hrow * 8;
                if (r < NN) {
                    float2 o;
                    o.x = acc[mt][nt][hrow * 2 + 0] + b0;
                    o.y = acc[mt][nt][hrow * 2 + 1] + b1;
                    if (MODE == 2) {
                        const float2 h = *reinterpret_cast<const float2*>(&g_h[(size_t)r * 128 + cc]);
                        o.x = fmaxf(o.x + h.x, 0.f);
                        o.y = fmaxf(o.y + h.y, 0.f);
                    }
                    *reinterpret_cast<float2*>(&C[(size_t)r * LDC + cc]) = o;
                    if (MODE == 0 || MODE == 2)
                        g_hb[((size_t)r * 128 + cc) >> 1] = cvt2(o.x, o.y);
                    if (MODE == 1) {
                        cs0 += o.x; cq0 = fmaf(o.x, o.x, cq0);
                        cs1 += o.y; cq1 = fmaf(o.y, o.y, cq1);
                    }
                }
            }
        }
        if (MODE == 1) {
            atomicAdd(&s_sum[ccl],       cs0);
            atomicAdd(&s_sum[ccl + 1],   cs1);
            atomicAdd(&s_sumsq[ccl],     cq0);
            atomicAdd(&s_sumsq[ccl + 1], cq1);
        }
    }
    if (MODE == 1) {
        __syncthreads();
        if (tid < 128) {
            atomicAdd(&g_sum[bn + tid],   (double)s_sum[tid]);
            atomicAdd(&g_sumsq[bn + tid], (double)s_sumsq[tid]);
        }
    }
}

// ---------------- small utility kernels -----------------------------------
__global__ void zero_pool_kernel() {
    int i = blockIdx.x * 256 + threadIdx.x;
    g_pool[i] = 0.f;
    if (i < 2 * GG) g_cnt[i] = 0.f;
}

// warp per edge: gather bf16 row (256B), vector-reduce fp32 into agg[dst];
// block 0 zeroes the BN accumulators for the upcoming MODE1.
__global__ void scatter_kernel(const int* __restrict__ ei) {
    int idx = blockIdx.x * 256 + threadIdx.x;  // 200000 x 256 (== E*32)
    if (blockIdx.x == 0) { g_sum[threadIdx.x] = 0.0; g_sumsq[threadIdx.x] = 0.0; }
    int e = idx >> 5;
    int c = idx & 31;
    int src = __ldg(&ei[e]);
    int dst = __ldg(&ei[EE + e]);
    uint2 v = *reinterpret_cast<const uint2*>(&g_hb[src * 64 + c * 2]);
    float f0 = __uint_as_float(v.x << 16);
    float f1 = __uint_as_float(v.x & 0xFFFF0000u);
    float f2 = __uint_as_float(v.y << 16);
    float f3 = __uint_as_float(v.y & 0xFFFF0000u);
    float* p = &g_agg[dst * 128 + c * 4];
    asm volatile("red.global.add.v4.f32 [%0], {%1,%2,%3,%4};"
                 :: "l"(p), "f"(f0), "f"(f1), "f"(f2), "f"(f3) : "memory");
}

__global__ void bn_finalize_kernel(const float* __restrict__ gam,
                                   const float* __restrict__ bet) {
    int c = threadIdx.x;   // 256
    float mean = (float)(g_sum[c] / (double)NN);
    float var  = (float)(g_sumsq[c] / (double)NN) - mean * mean;
    float sc = gam[c] * rsqrtf(var + 1e-5f);
    g_scale[c] = sc;
    g_shift[c] = fmaf(-mean, sc, bet[c]);
}

__global__ void pool_kernel(const int* __restrict__ batch, int which) {
    int idx = blockIdx.x * 256 + threadIdx.x;   // 12500 x 256 (== N*32)
    int n = idx >> 5;
    int c = (idx & 31) << 2;
    int g = __ldg(&batch[n]);
    float4 v = *reinterpret_cast<const float4*>(&g_h[n * 128 + c]);
    float* p = &g_pool[(which * GG + g) * 128 + c];
    asm volatile("red.global.add.v4.f32 [%0], {%1,%2,%3,%4};"
                 :: "l"(p), "f"(v.x), "f"(v.y), "f"(v.z), "f"(v.w) : "memory");
    if ((idx & 31) == 0) atomicAdd(&g_cnt[which * GG + g], 1.0f);
}

__global__ void head1_kernel(const float* __restrict__ W, const float* __restrict__ b) {
    int g = blockIdx.x, j = threadIdx.x;   // 64 x 256
    __shared__ float xc[256];
    if (j < 128) xc[j] = g_pool[g * 128 + j] / fmaxf(g_cnt[g], 1.0f);
    else         xc[j] = g_pool[(GG + g) * 128 + (j - 128)] / fmaxf(g_cnt[GG + g], 1.0f);
    __syncthreads();
    float acc = b[j];
#pragma unroll 8
    for (int k = 0; k < 256; k++) acc = fmaf(xc[k], W[k * 256 + j], acc);
    g_fc1o[g * 256 + j] = fmaxf(acc, 0.f);
}

__global__ void head2_kernel(const float* __restrict__ W, const float* __restrict__ b) {
    int g = blockIdx.x, j = threadIdx.x;   // 64 x 64
    __shared__ float xin[256];
    for (int k = j; k < 256; k += 64) xin[k] = g_fc1o[g * 256 + k];
    __syncthreads();
    float acc = b[j];
#pragma unroll 8
    for (int k = 0; k < 256; k++) acc = fmaf(xin[k], W[k * 64 + j], acc);
    g_fc2o[g * 64 + j] = fmaxf(acc, 0.f);
}

__global__ void head3_kernel(const float* __restrict__ W, const float* __restrict__ b,
                             float* __restrict__ out) {
    int g = threadIdx.x;   // 1 x 64
    float acc = b[0];
#pragma unroll
    for (int k = 0; k < 64; k++) acc = fmaf(g_fc2o[g * 64 + k], W[k], acc);
    out[g] = 1.0f / (1.0f + expf(-acc));
}

// ---------------- orchestration -------------------------------------------
extern "C" void kernel_launch(void* const* d_in, const int* in_sizes, int n_in,
                              void* d_out, int out_size) {
    const float* x[2]     = { (const float*)d_in[0], (const float*)d_in[3] };
    const int*   ei[2]    = { (const int*)d_in[1],   (const int*)d_in[4] };
    const int*   batch[2] = { (const int*)d_in[2],   (const int*)d_in[5] };

    void* aggp = nullptr;
    cudaGetSymbolAddress(&aggp, g_agg);

    const int GRID_M = (NN + 127) / 128;   // 782

    zero_pool_kernel<<<64, 256>>>();

    for (int b = 0; b < 2; b++) {
        int o = 6 + b * 9;
        const float* embW = (const float*)d_in[o + 0];
        const float* embB = (const float*)d_in[o + 1];
        const float* W1   = (const float*)d_in[o + 2];
        const float* b1   = (const float*)d_in[o + 3];
        const float* gam  = (const float*)d_in[o + 4];
        const float* bet  = (const float*)d_in[o + 5];
        const float* W2   = (const float*)d_in[o + 6];
        const float* b2   = (const float*)d_in[o + 7];
        const float* eps  = (const float*)d_in[o + 8];

        mma_gemm<0><<<dim3(GRID_M, 1), 256>>>(x[b], embW, embB, nullptr);

        for (int i = 0; i < 4; i++) {
            cudaMemsetAsync(aggp, 0, (size_t)NN * 128 * sizeof(float), 0);
            scatter_kernel<<<200000, 256>>>(ei[b]);
            mma_gemm<1><<<dim3(GRID_M, 2), 256>>>(nullptr, W1 + (size_t)i * 128 * 256,
                                                  b1 + i * 256, eps + i);
            bn_finalize_kernel<<<1, 256>>>(gam + i * 256, bet + i * 256);
            mma_gemm<2><<<dim3(GRID_M, 1), 256>>>(nullptr, W2 + (size_t)i * 256 * 128,
                                                  b2 + i * 128, nullptr);
        }
        pool_kernel<<<12500, 256>>>(batch[b], b);
    }

    head1_kernel<<<64, 256>>>((const float*)d_in[24], (const float*)d_in[25]);
    head2_kernel<<<64, 64>>>((const float*)d_in[26], (const float*)d_in[27]);
    head3_kernel<<<1, 64>>>((const float*)d_in[28], (const float*)d_in[29], (float*)d_out);
}